// round 11
// baseline (speedup 1.0000x reference)
#include <cuda_runtime.h>
#include <cuda_fp16.h>
#include <cstdint>

// ---------------- problem dims ----------------
#define CIN   32
#define COUT  32
#define HIN   512
#define WIN   512
#define HOUT  510
#define WOUT  510
#define NB    16

// ---------------- tiling ----------------
#define TY      4              // output rows per tile
#define TPX     64             // output px per CTA
#define XPX     68             // staged px (64 + 2 halo + pad)
#define THREADS 384            // 8 compute warps + 4 loader warps
#define NTILES  8              // y-tiles walked per CTA

// ---------------- smem ----------------
// rows of 80B (64B = 32 ci fp16 + 16B pad): conflict-free for LDSM & STS128
#define ROWB       80
#define XSLOT      (XPX * ROWB)         // 5440
#define XBUF       (6 * XSLOT)          // 32640 (one 6-row buffer)
#define W_OFF      (2 * XBUF)           // 65280
#define W_BYTES    (288 * ROWB)         // 23040 (rows: kk*32+co)
#define SMEM_TOTAL (W_OFF + W_BYTES)    // 88320

// pre-packed weights: [kk*32+co][40 halves] (32 ci + 8 pad)
__device__ __align__(16) __half w_packed[288 * 40];

__device__ __forceinline__ uint32_t smem_u32(const void* p) {
    uint32_t a;
    asm("{ .reg .u64 t; cvta.to.shared.u64 t, %1; cvt.u32.u64 %0, t; }"
        : "=r"(a) : "l"(p));
    return a;
}
__device__ __forceinline__ uint32_t h2u(__half2 h) {
    return *reinterpret_cast<uint32_t*>(&h);
}

#define STS128(addr, a, b, c, d) \
    asm volatile("st.shared.v4.b32 [%0], {%1,%2,%3,%4};" \
        :: "r"(addr), "r"(a), "r"(b), "r"(c), "r"(d) : "memory")

#define LDSM4(r, addr) \
    asm volatile("ldmatrix.sync.aligned.m8n8.x4.shared.b16 {%0,%1,%2,%3}, [%4];" \
        : "=r"((r)[0]), "=r"((r)[1]), "=r"((r)[2]), "=r"((r)[3]) : "r"(addr))

#define MMA_F16(c, a, b0, b1) \
    asm volatile("mma.sync.aligned.m16n8k16.row.col.f32.f16.f16.f32 " \
        "{%0,%1,%2,%3}, {%4,%5,%6,%7}, {%8,%9}, {%0,%1,%2,%3};" \
        : "+f"((c)[0]), "+f"((c)[1]), "+f"((c)[2]), "+f"((c)[3]) \
        : "r"((a)[0]), "r"((a)[1]), "r"((a)[2]), "r"((a)[3]), "r"(b0), "r"(b1))

// =====================================================================
// setup: w (OIHW fp32) -> w_packed [kk][co][ci] fp16, 80B rows
// =====================================================================
__global__ void pack_w_kernel(const float* __restrict__ w)
{
    int i = blockIdx.x * 256 + threadIdx.x;
    if (i < 288 * 32) {
        int row = i >> 5;                  // kk*32+co
        int ci  = i & 31;
        int kk  = row >> 5;
        int co  = row & 31;
        w_packed[row * 40 + ci] = __float2half_rn(w[(co * 32 + ci) * 9 + kk]);
    }
}

// =====================================================================
// stage one 6-row X tile (pairs = row-slot*4 + ci-octet)
// =====================================================================
__device__ __forceinline__ void stage_x(const float* __restrict__ x,
                                        int nb, int x0, int yin0,
                                        uint32_t bufbase,
                                        int pstart, int pstride, int lane)
{
    #pragma unroll 1
    for (int pair = pstart; pair < 24; pair += pstride) {
        const int s = pair >> 2;
        const int o = pair & 3;
        const int y_in = yin0 + s;
        const bool yok = (y_in < HIN);
        const float* xp =
            x + ((size_t)(nb * CIN + o * 8) * HIN + y_in) * WIN + x0;
        const uint32_t rbase = bufbase + (uint32_t)s * XSLOT + (uint32_t)o * 16;
        #pragma unroll
        for (int p0 = 0; p0 < XPX; p0 += 32) {
            const int px = p0 + lane;
            if (px < XPX) {
                const bool ok = yok && (x0 + px) < WIN;
                float v[8];
                #pragma unroll
                for (int j = 0; j < 8; ++j)
                    v[j] = ok ? xp[(size_t)j * HIN * WIN + px] : 0.0f;
                __half2 h0 = __floats2half2_rn(v[0], v[1]);
                __half2 h1 = __floats2half2_rn(v[2], v[3]);
                __half2 h2 = __floats2half2_rn(v[4], v[5]);
                __half2 h3 = __floats2half2_rn(v[6], v[7]);
                STS128(rbase + (uint32_t)px * ROWB,
                       h2u(h0), h2u(h1), h2u(h2), h2u(h3));
            }
        }
    }
}

// =====================================================================
// main kernel: warp-specialized, double-buffered, persistent over 8 y-tiles
// =====================================================================
__global__ __launch_bounds__(THREADS, 1)
void conv_mma_kernel(const float* __restrict__ x,
                     const float* __restrict__ bias,
                     float* __restrict__ out)
{
    extern __shared__ char smem[];
    const uint32_t sb = smem_u32(smem);
    const int t    = threadIdx.x;
    const int wid  = t >> 5;
    const int lane = t & 31;

    const int xt = blockIdx.x;            // 0..7
    const int gy = blockIdx.y;            // 0..15
    const int nb = blockIdx.z;            // 0..15
    const int x0 = xt * TPX;
    const int yt0 = gy * NTILES;          // first y-tile index

    // ---- stage W once (all warps): straight 16B copy of pre-packed layout
    {
        const uint4* src = reinterpret_cast<const uint4*>(w_packed);
        #pragma unroll 1
        for (int i = t; i < W_BYTES / 16; i += THREADS) {
            uint4 v = src[i];
            STS128(sb + W_OFF + (uint32_t)i * 16, v.x, v.y, v.z, v.w);
        }
    }
    // ---- prologue: stage tile 0 into buf 0 (all 12 warps)
    stage_x(x, nb, x0, yt0 * TY, sb, wid, 12, lane);
    __syncthreads();

    // lane constants (compute warps)
    const int a_row   = lane & 15;
    const int a_chunk = lane >> 4;
    const int b_n     = (lane & 7) | ((lane >> 4) << 3);
    const int b_chunk = (lane >> 3) & 1;
    const int g  = lane >> 2;
    const int tg = lane & 3;

    float bv[2][2];
    #pragma unroll
    for (int mt = 0; mt < 2; ++mt) {
        bv[mt][0] = __ldg(bias + mt * 16 + g);
        bv[mt][1] = __ldg(bias + mt * 16 + 8 + g);
    }

    #pragma unroll 1
    for (int i = 0; i < NTILES; ++i) {
        const uint32_t bufOff = (uint32_t)(i & 1) * XBUF;

        if (wid < 8) {
            // ---- compute tile yt0+i on buf (i&1)
            const int r   = wid >> 1;
            const int pxw = (wid & 1) * 32;

            float c[2][4][4];
            #pragma unroll
            for (int mt = 0; mt < 2; ++mt)
                #pragma unroll
                for (int q = 0; q < 4; ++q) {
                    c[mt][q][0] = bv[mt][0]; c[mt][q][1] = bv[mt][0];
                    c[mt][q][2] = bv[mt][1]; c[mt][q][3] = bv[mt][1];
                }

            #pragma unroll
            for (int ky = 0; ky < 3; ++ky) {
                const uint32_t Xs = sb + bufOff + (uint32_t)(r + ky) * XSLOT;
                #pragma unroll
                for (int kx = 0; kx < 3; ++kx) {
                    const int kk = ky * 3 + kx;
                    const uint32_t aBase =
                        sb + W_OFF + (uint32_t)(kk * 32 + a_row) * ROWB;
                    #pragma unroll
                    for (int kc = 0; kc < 2; ++kc) {
                        const uint32_t aOff = (uint32_t)(2 * kc + a_chunk) * 16;
                        const uint32_t bOff = (uint32_t)(2 * kc + b_chunk) * 16;

                        uint32_t a[2][4];
                        LDSM4(a[0], aBase + aOff);
                        LDSM4(a[1], aBase + 16 * ROWB + aOff);

                        uint32_t b[2][4];
                        #pragma unroll
                        for (int g2 = 0; g2 < 2; ++g2) {
                            const int prow = pxw + kx + g2 * 16 + b_n;
                            LDSM4(b[g2], Xs + (uint32_t)prow * ROWB + bOff);
                        }
                        #pragma unroll
                        for (int mt = 0; mt < 2; ++mt)
                            #pragma unroll
                            for (int q = 0; q < 4; ++q) {
                                const int g2 = q >> 1;
                                const int e  = (q & 1) * 2;
                                MMA_F16(c[mt][q], a[mt], b[g2][e], b[g2][e + 1]);
                            }
                    }
                }
            }

            // ---- store
            const int oy = (yt0 + i) * TY + r;
            if (oy < HOUT) {
                #pragma unroll
                for (int mt = 0; mt < 2; ++mt) {
                    const size_t base0 =
                        ((size_t)(nb * COUT + mt * 16 + g) * HOUT + oy) * (size_t)WOUT;
                    const size_t coStep = (size_t)8 * HOUT * WOUT;
                    #pragma unroll
                    for (int q = 0; q < 4; ++q) {
                        const int ox = x0 + pxw + q * 8 + 2 * tg;
                        if (ox < WOUT) {
                            float2 v0 = make_float2(c[mt][q][0], c[mt][q][1]);
                            float2 v1 = make_float2(c[mt][q][2], c[mt][q][3]);
                            *reinterpret_cast<float2*>(out + base0 + ox)          = v0;
                            *reinterpret_cast<float2*>(out + base0 + coStep + ox) = v1;
                        }
                    }
                }
            }
        } else if (i + 1 < NTILES) {
            // ---- loaders: stage tile i+1 into the other buffer
            stage_x(x, nb, x0, (yt0 + i + 1) * TY,
                    sb + (bufOff ^ XBUF), wid - 8, 4, lane);
        }
        __syncthreads();
    }
}

extern "C" void kernel_launch(void* const* d_in, const int* in_sizes, int n_in,
                              void* d_out, int out_size)
{
    const float* x    = (const float*)d_in[0];
    const float* w    = (const float*)d_in[1];
    const float* bias = (const float*)d_in[2];
    float*       out  = (float*)d_out;

    pack_w_kernel<<<36, 256>>>(w);

    cudaFuncSetAttribute(conv_mma_kernel,
                         cudaFuncAttributeMaxDynamicSharedMemorySize, SMEM_TOTAL);

    dim3 grid(8, 16, NB);    // 8 x-tiles, 16 y-walks of 8 tiles, 16 batches
    conv_mma_kernel<<<grid, THREADS, SMEM_TOTAL>>>(x, bias, out);
}

// round 12
// speedup vs baseline: 1.5225x; 1.5225x over previous
#include <cuda_runtime.h>
#include <cuda_fp16.h>
#include <cstdint>

// ---------------- problem dims ----------------
#define CIN   32
#define COUT  32
#define HIN   512
#define WIN   512
#define HOUT  510
#define WOUT  510
#define NB    16

// ---------------- tiling ----------------
#define TY      4              // output rows per CTA
#define TPX     128            // output px per CTA
#define XPX     132            // staged px (128 + 2 halo + pad)
#define THREADS 256

// ---------------- smem ----------------
// rows of 80B (64B = 32 ci fp16 + 16B pad): conflict-free for LDSM & STS128
#define ROWB       80
#define XSLOT      (XPX * ROWB)         // 10560
#define W_OFF      (6 * XSLOT)          // 63360
#define W_BYTES    (288 * ROWB)         // 23040 (rows: kk*32+co)
#define SMEM_TOTAL (W_OFF + W_BYTES)    // 86400  (2 CTAs/SM: 172.8KB <= 227KB)

// pre-packed weights: [kk*32+co][40 halves] (32 ci + 8 pad)
__device__ __align__(16) __half w_packed[288 * 40];

__device__ __forceinline__ uint32_t smem_u32(const void* p) {
    uint32_t a;
    asm("{ .reg .u64 t; cvta.to.shared.u64 t, %1; cvt.u32.u64 %0, t; }"
        : "=r"(a) : "l"(p));
    return a;
}
__device__ __forceinline__ uint32_t h2u(__half2 h) {
    return *reinterpret_cast<uint32_t*>(&h);
}

#define STS128(addr, a, b, c, d) \
    asm volatile("st.shared.v4.b32 [%0], {%1,%2,%3,%4};" \
        :: "r"(addr), "r"(a), "r"(b), "r"(c), "r"(d) : "memory")

#define LDSM4(r, addr) \
    asm volatile("ldmatrix.sync.aligned.m8n8.x4.shared.b16 {%0,%1,%2,%3}, [%4];" \
        : "=r"((r)[0]), "=r"((r)[1]), "=r"((r)[2]), "=r"((r)[3]) : "r"(addr))

#define MMA_F16(c, a, b0, b1) \
    asm volatile("mma.sync.aligned.m16n8k16.row.col.f32.f16.f16.f32 " \
        "{%0,%1,%2,%3}, {%4,%5,%6,%7}, {%8,%9}, {%0,%1,%2,%3};" \
        : "+f"((c)[0]), "+f"((c)[1]), "+f"((c)[2]), "+f"((c)[3]) \
        : "r"((a)[0]), "r"((a)[1]), "r"((a)[2]), "r"((a)[3]), "r"(b0), "r"(b1))

// =====================================================================
// setup: w (OIHW fp32) -> w_packed [kk][co][ci] fp16, 80B rows
// =====================================================================
__global__ void pack_w_kernel(const float* __restrict__ w)
{
    int i = blockIdx.x * 256 + threadIdx.x;
    if (i < 288 * 32) {
        int row = i >> 5;                  // kk*32+co
        int ci  = i & 31;
        int kk  = row >> 5;
        int co  = row & 31;
        w_packed[row * 40 + ci] = __float2half_rn(w[(co * 32 + ci) * 9 + kk]);
    }
}

// =====================================================================
// main kernel: fp16 implicit-GEMM conv, m32n64 warp tiles
// =====================================================================
__global__ __launch_bounds__(THREADS, 2)
void conv_mma_kernel(const float* __restrict__ x,
                     const float* __restrict__ bias,
                     float* __restrict__ out)
{
    extern __shared__ char smem[];
    const uint32_t sb = smem_u32(smem);
    const int t    = threadIdx.x;
    const int wid  = t >> 5;
    const int lane = t & 31;

    const int xt = blockIdx.x;       // 0..3
    const int yt = blockIdx.y;       // 0..127
    const int nb = blockIdx.z;       // 0..15
    const int x0 = xt * TPX;
    const int y0 = yt * TY;

    // ---- stage W: straight 16B copy of pre-packed layout
    {
        const uint4* src = reinterpret_cast<const uint4*>(w_packed);
        #pragma unroll 1
        for (int i = t; i < W_BYTES / 16; i += THREADS) {
            uint4 v = src[i];
            STS128(sb + W_OFF + (uint32_t)i * 16, v.x, v.y, v.z, v.w);
        }
    }

    // ---- stage X: (6 rows x 4 ci-octets) over 8 warps, 132 px each
    #pragma unroll 1
    for (int pair = wid; pair < 24; pair += 8) {
        const int s = pair >> 2;            // input row 0..5
        const int o = pair & 3;             // ci octet
        const int y_in = y0 + s;
        const bool yok = (y_in < HIN);
        const float* xp =
            x + ((size_t)(nb * CIN + o * 8) * HIN + y_in) * WIN + x0;
        const uint32_t rbase = sb + (uint32_t)s * XSLOT + (uint32_t)o * 16;
        #pragma unroll
        for (int p0 = 0; p0 < XPX; p0 += 32) {
            const int px = p0 + lane;
            if (px < XPX) {
                const bool ok = yok && (x0 + px) < WIN;
                float v[8];
                #pragma unroll
                for (int j = 0; j < 8; ++j)
                    v[j] = ok ? xp[(size_t)j * HIN * WIN + px] : 0.0f;
                __half2 h0 = __floats2half2_rn(v[0], v[1]);
                __half2 h1 = __floats2half2_rn(v[2], v[3]);
                __half2 h2 = __floats2half2_rn(v[4], v[5]);
                __half2 h3 = __floats2half2_rn(v[6], v[7]);
                STS128(rbase + (uint32_t)px * ROWB,
                       h2u(h0), h2u(h1), h2u(h2), h2u(h3));
            }
        }
    }
    __syncthreads();

    // ---- mainloop: warp = (row, 64-px chunk), m32 x n64, fp16 k16
    const int r   = wid >> 1;          // output row 0..3
    const int pxw = (wid & 1) * 64;    // px chunk base

    const int a_row   = lane & 15;           // A: co row within m16
    const int a_chunk = lane >> 4;           // A: k8 chunk 0/1
    const int b_n     = (lane & 7) | ((lane >> 4) << 3);   // B: px within 16
    const int b_chunk = (lane >> 3) & 1;                   // B: k8 chunk 0/1

    const int g  = lane >> 2;
    const int tg = lane & 3;

    float c[2][8][4];                  // [m16 half][n8 group][frag]
    #pragma unroll
    for (int mt = 0; mt < 2; ++mt) {
        const float bv0 = __ldg(bias + mt * 16 + g);
        const float bv1 = __ldg(bias + mt * 16 + 8 + g);
        #pragma unroll
        for (int q = 0; q < 8; ++q) {
            c[mt][q][0] = bv0; c[mt][q][1] = bv0;
            c[mt][q][2] = bv1; c[mt][q][3] = bv1;
        }
    }

    #pragma unroll
    for (int ky = 0; ky < 3; ++ky) {
        const uint32_t Xs = sb + (uint32_t)(r + ky) * XSLOT;
        #pragma unroll
        for (int kx = 0; kx < 3; ++kx) {
            const int kk = ky * 3 + kx;
            const uint32_t aBase =
                sb + W_OFF + (uint32_t)(kk * 32 + a_row) * ROWB;
            #pragma unroll
            for (int kc = 0; kc < 2; ++kc) {       // two k16 steps over 32 ci
                const uint32_t aOff = (uint32_t)(2 * kc + a_chunk) * 16;
                const uint32_t bOff = (uint32_t)(2 * kc + b_chunk) * 16;

                uint32_t a[2][4];
                LDSM4(a[0], aBase + aOff);
                LDSM4(a[1], aBase + 16 * ROWB + aOff);

                uint32_t b[4][4];
                #pragma unroll
                for (int g2 = 0; g2 < 4; ++g2) {   // four n16 groups
                    const int prow = pxw + kx + g2 * 16 + b_n;
                    LDSM4(b[g2], Xs + (uint32_t)prow * ROWB + bOff);
                }

                #pragma unroll
                for (int mt = 0; mt < 2; ++mt)
                    #pragma unroll
                    for (int q = 0; q < 8; ++q) {
                        const int g2 = q >> 1;
                        const int e  = (q & 1) * 2;
                        MMA_F16(c[mt][q], a[mt], b[g2][e], b[g2][e + 1]);
                    }
            }
        }
    }

    // ---- store (fp32 float2, guarded at edges)
    const int oy = y0 + r;
    if (oy < HOUT) {
        #pragma unroll
        for (int mt = 0; mt < 2; ++mt) {
            const size_t base0 =
                ((size_t)(nb * COUT + mt * 16 + g) * HOUT + oy) * (size_t)WOUT;
            const size_t coStep = (size_t)8 * HOUT * WOUT;
            #pragma unroll
            for (int q = 0; q < 8; ++q) {
                const int ox = x0 + pxw + q * 8 + 2 * tg;
                if (ox < WOUT) {
                    float2 v0 = make_float2(c[mt][q][0], c[mt][q][1]);
                    float2 v1 = make_float2(c[mt][q][2], c[mt][q][3]);
                    *reinterpret_cast<float2*>(out + base0 + ox)          = v0;
                    *reinterpret_cast<float2*>(out + base0 + coStep + ox) = v1;
                }
            }
        }
    }
}

extern "C" void kernel_launch(void* const* d_in, const int* in_sizes, int n_in,
                              void* d_out, int out_size)
{
    const float* x    = (const float*)d_in[0];
    const float* w    = (const float*)d_in[1];
    const float* bias = (const float*)d_in[2];
    float*       out  = (float*)d_out;

    pack_w_kernel<<<36, 256>>>(w);

    cudaFuncSetAttribute(conv_mma_kernel,
                         cudaFuncAttributeMaxDynamicSharedMemorySize, SMEM_TOTAL);

    dim3 grid((WOUT + TPX - 1) / TPX,   // 4
              (HOUT + TY - 1) / TY,     // 128
              NB);                      // 16
    conv_mma_kernel<<<grid, THREADS, SMEM_TOTAL>>>(x, bias, out);
}

// round 13
// speedup vs baseline: 1.7837x; 1.1716x over previous
#include <cuda_runtime.h>
#include <cuda_fp16.h>
#include <cstdint>

// ---------------- problem dims ----------------
#define CIN   32
#define COUT  32
#define HIN   512
#define WIN   512
#define HOUT  510
#define WOUT  510
#define NB    16

// ---------------- tiling ----------------
#define TY      4              // output rows per tile
#define TPX     64             // output px per CTA
#define XPX     68             // staged px (64 + 2 halo + pad)
#define THREADS 256
#define NTILES  8              // y-tiles walked per CTA

// ---------------- smem ----------------
// rows of 80B (64B = 32 ci fp16 + 16B pad): conflict-free for LDSM
#define ROWB       80
#define XSLOT      (XPX * ROWB)         // 5440
#define XBUF       (6 * XSLOT)          // 32640
#define W_OFF      (2 * XBUF)           // 65280
#define W_BYTES    (288 * ROWB)         // 23040
#define SMEM_TOTAL (W_OFF + W_BYTES)    // 88320 (2 CTAs/SM)

// pre-packed weights: [kk*32+co][40 halves] (32 ci + 8 pad)
__device__ __align__(16) __half w_packed[288 * 40];
// x converted to fp16 NHWC: [nb][y][x][ci]  (256 MB)
__device__ __align__(16) __half xh_g[(size_t)NB * HIN * WIN * CIN];

__device__ __forceinline__ uint32_t smem_u32(const void* p) {
    uint32_t a;
    asm("{ .reg .u64 t; cvta.to.shared.u64 t, %1; cvt.u32.u64 %0, t; }"
        : "=r"(a) : "l"(p));
    return a;
}

#define STS128(addr, a, b, c, d) \
    asm volatile("st.shared.v4.b32 [%0], {%1,%2,%3,%4};" \
        :: "r"(addr), "r"(a), "r"(b), "r"(c), "r"(d) : "memory")

#define LDSM4(r, addr) \
    asm volatile("ldmatrix.sync.aligned.m8n8.x4.shared.b16 {%0,%1,%2,%3}, [%4];" \
        : "=r"((r)[0]), "=r"((r)[1]), "=r"((r)[2]), "=r"((r)[3]) : "r"(addr))

#define MMA_F16(c, a, b0, b1) \
    asm volatile("mma.sync.aligned.m16n8k16.row.col.f32.f16.f16.f32 " \
        "{%0,%1,%2,%3}, {%4,%5,%6,%7}, {%8,%9}, {%0,%1,%2,%3};" \
        : "+f"((c)[0]), "+f"((c)[1]), "+f"((c)[2]), "+f"((c)[3]) \
        : "r"((a)[0]), "r"((a)[1]), "r"((a)[2]), "r"((a)[3]), "r"(b0), "r"(b1))

#define CP_ASYNC16(smem, gmem) \
    asm volatile("cp.async.cg.shared.global [%0], [%1], 16;" \
        :: "r"(smem), "l"(gmem) : "memory")
#define CP_COMMIT()  asm volatile("cp.async.commit_group;" ::: "memory")
#define CP_WAIT0()   asm volatile("cp.async.wait_group 0;" ::: "memory")

// =====================================================================
// setup 1: w (OIHW fp32) -> w_packed [kk][co][ci] fp16
// =====================================================================
__global__ void pack_w_kernel(const float* __restrict__ w)
{
    int i = blockIdx.x * 256 + threadIdx.x;
    if (i < 288 * 32) {
        int row = i >> 5;                  // kk*32+co
        int ci  = i & 31;
        int kk  = row >> 5;
        int co  = row & 31;
        w_packed[row * 40 + ci] = __float2half_rn(w[(co * 32 + ci) * 9 + kk]);
    }
}

// =====================================================================
// setup 2: x (NCHW fp32) -> xh_g (NHWC fp16), pure streaming transpose
// =====================================================================
__global__ __launch_bounds__(256)
void convert_x_kernel(const float* __restrict__ x)
{
    const int px = blockIdx.x * 256 + threadIdx.x;   // 0..511
    const int y  = blockIdx.y;
    const int nb = blockIdx.z;

    const float* xp = x + ((size_t)(nb * CIN) * HIN + y) * WIN + px;
    __half hv[CIN];
    #pragma unroll
    for (int ci = 0; ci < CIN; ++ci)
        hv[ci] = __float2half_rn(xp[(size_t)ci * HIN * WIN]);

    uint4* dst = reinterpret_cast<uint4*>(
        xh_g + (((size_t)nb * HIN + y) * WIN + px) * CIN);
    const uint4* src = reinterpret_cast<const uint4*>(hv);
    #pragma unroll
    for (int j = 0; j < 4; ++j) dst[j] = src[j];
}

// =====================================================================
// main kernel: cp.async double-buffered persistent fp16 implicit GEMM
// =====================================================================
__device__ __forceinline__ void issue_tile(uint32_t dstbase, int nb,
                                           int x0, int y0, int t)
{
    // 6 rows x 68 px x 4 16B-chunks = 1632 chunks
    #pragma unroll 1
    for (int chunk = t; chunk < 6 * XPX * 4; chunk += THREADS) {
        const int c  = chunk & 3;
        const int pq = chunk >> 2;
        const int s  = pq / XPX;
        const int px = pq - s * XPX;
        const int y_in = y0 + s;
        const int gx   = x0 + px;
        if (y_in < HIN && gx < WIN) {
            const __half* g =
                xh_g + (((size_t)nb * HIN + y_in) * WIN + gx) * CIN + c * 8;
            CP_ASYNC16(dstbase + (uint32_t)s * XSLOT + (uint32_t)px * ROWB
                               + (uint32_t)c * 16,
                       g);
        }
    }
}

__global__ __launch_bounds__(THREADS, 2)
void conv_mma_kernel(const float* __restrict__ bias,
                     float* __restrict__ out)
{
    extern __shared__ char smem[];
    const uint32_t sb = smem_u32(smem);
    const int t    = threadIdx.x;
    const int wid  = t >> 5;
    const int lane = t & 31;

    const int xt  = blockIdx.x;           // 0..7
    const int gy  = blockIdx.y;           // 0..15
    const int nb  = blockIdx.z;           // 0..15
    const int x0  = xt * TPX;
    const int yt0 = gy * NTILES;

    // ---- stage W once per CTA
    {
        const uint4* src = reinterpret_cast<const uint4*>(w_packed);
        #pragma unroll 1
        for (int i = t; i < W_BYTES / 16; i += THREADS) {
            uint4 v = src[i];
            STS128(sb + W_OFF + (uint32_t)i * 16, v.x, v.y, v.z, v.w);
        }
    }

    // ---- prologue: async-copy tile 0 into buf 0
    issue_tile(sb, nb, x0, yt0 * TY, t);
    CP_COMMIT();
    CP_WAIT0();
    __syncthreads();

    // lane constants
    const int a_row   = lane & 15;
    const int a_chunk = lane >> 4;
    const int b_n     = (lane & 7) | ((lane >> 4) << 3);
    const int b_chunk = (lane >> 3) & 1;
    const int g  = lane >> 2;
    const int tg = lane & 3;

    const int r   = wid >> 1;          // output row 0..3
    const int pxw = (wid & 1) * 32;    // px chunk base

    float bv[2][2];
    #pragma unroll
    for (int mt = 0; mt < 2; ++mt) {
        bv[mt][0] = __ldg(bias + mt * 16 + g);
        bv[mt][1] = __ldg(bias + mt * 16 + 8 + g);
    }

    #pragma unroll 1
    for (int i = 0; i < NTILES; ++i) {
        const uint32_t bufOff = (uint32_t)(i & 1) * XBUF;

        // ---- issue copies for next tile into the other buffer
        if (i + 1 < NTILES) {
            issue_tile(sb + (bufOff ^ XBUF), nb, x0, (yt0 + i + 1) * TY, t);
            CP_COMMIT();
        }

        // ---- compute tile i
        float c[2][4][4];
        #pragma unroll
        for (int mt = 0; mt < 2; ++mt)
            #pragma unroll
            for (int q = 0; q < 4; ++q) {
                c[mt][q][0] = bv[mt][0]; c[mt][q][1] = bv[mt][0];
                c[mt][q][2] = bv[mt][1]; c[mt][q][3] = bv[mt][1];
            }

        #pragma unroll
        for (int ky = 0; ky < 3; ++ky) {
            const uint32_t Xs = sb + bufOff + (uint32_t)(r + ky) * XSLOT;
            #pragma unroll
            for (int kx = 0; kx < 3; ++kx) {
                const int kk = ky * 3 + kx;
                const uint32_t aBase =
                    sb + W_OFF + (uint32_t)(kk * 32 + a_row) * ROWB;
                #pragma unroll
                for (int kc = 0; kc < 2; ++kc) {
                    const uint32_t aOff = (uint32_t)(2 * kc + a_chunk) * 16;
                    const uint32_t bOff = (uint32_t)(2 * kc + b_chunk) * 16;

                    uint32_t a[2][4];
                    LDSM4(a[0], aBase + aOff);
                    LDSM4(a[1], aBase + 16 * ROWB + aOff);

                    uint32_t b[2][4];
                    #pragma unroll
                    for (int g2 = 0; g2 < 2; ++g2) {
                        const int prow = pxw + kx + g2 * 16 + b_n;
                        LDSM4(b[g2], Xs + (uint32_t)prow * ROWB + bOff);
                    }
                    #pragma unroll
                    for (int mt = 0; mt < 2; ++mt)
                        #pragma unroll
                        for (int q = 0; q < 4; ++q) {
                            const int g2 = q >> 1;
                            const int e  = (q & 1) * 2;
                            MMA_F16(c[mt][q], a[mt], b[g2][e], b[g2][e + 1]);
                        }
                }
            }
        }

        // ---- store
        const int oy = (yt0 + i) * TY + r;
        if (oy < HOUT) {
            #pragma unroll
            for (int mt = 0; mt < 2; ++mt) {
                const size_t base0 =
                    ((size_t)(nb * COUT + mt * 16 + g) * HOUT + oy) * (size_t)WOUT;
                const size_t coStep = (size_t)8 * HOUT * WOUT;
                #pragma unroll
                for (int q = 0; q < 4; ++q) {
                    const int ox = x0 + pxw + q * 8 + 2 * tg;
                    if (ox < WOUT) {
                        float2 v0 = make_float2(c[mt][q][0], c[mt][q][1]);
                        float2 v1 = make_float2(c[mt][q][2], c[mt][q][3]);
                        *reinterpret_cast<float2*>(out + base0 + ox)          = v0;
                        *reinterpret_cast<float2*>(out + base0 + coStep + ox) = v1;
                    }
                }
            }
        }

        // ---- drain next-tile copies, flip buffers
        if (i + 1 < NTILES) CP_WAIT0();
        __syncthreads();
    }
}

extern "C" void kernel_launch(void* const* d_in, const int* in_sizes, int n_in,
                              void* d_out, int out_size)
{
    const float* x    = (const float*)d_in[0];
    const float* w    = (const float*)d_in[1];
    const float* bias = (const float*)d_in[2];
    float*       out  = (float*)d_out;

    pack_w_kernel<<<36, 256>>>(w);

    dim3 cgrid(WIN / 256, HIN, NB);     // (2, 512, 16)
    convert_x_kernel<<<cgrid, 256>>>(x);

    cudaFuncSetAttribute(conv_mma_kernel,
                         cudaFuncAttributeMaxDynamicSharedMemorySize, SMEM_TOTAL);

    dim3 grid(8, 16, NB);               // 8 x-tiles, 16 y-walks, 16 batches
    conv_mma_kernel<<<grid, THREADS, SMEM_TOTAL>>>(bias, out);
}

// round 14
// speedup vs baseline: 2.1740x; 1.2188x over previous
#include <cuda_runtime.h>
#include <cuda_fp16.h>
#include <cstdint>

// ---------------- problem dims ----------------
#define CIN   32
#define COUT  32
#define HIN   512
#define WIN   512
#define HOUT  510
#define WOUT  510
#define NB    16

// ---------------- tiling ----------------
#define TY      4              // output rows per tile
#define TPX     64             // output px per CTA
#define XPX     68             // staged px (64 + 2 halo + pad)
#define THREADS 256
#define NTILES  8              // y-tiles walked per CTA

// ---------------- smem ----------------
// fp16 ring rows of 80B (64B data + 16B pad): conflict-free LDSM/STS
#define ROWB       80
#define XSLOT      (XPX * ROWB)         // 5440
#define RSLOTS     10                   // ring of input-row slots
#define RING_BYTES (RSLOTS * XSLOT)     // 54400
// fp32 stage: [j<4][ci<32][68 px], row = 272B (16B-aligned for cp.async)
#define FROW       272
#define FSLOT      (32 * FROW)          // 8704 per input row
#define F_OFF      RING_BYTES           // 54400
#define F_BYTES    (4 * FSLOT)          // 34816
#define W_OFF      (F_OFF + F_BYTES)    // 89216
#define W_BYTES    (288 * ROWB)         // 23040
#define SMEM_TOTAL (W_OFF + W_BYTES)    // 112256 (2 CTAs/SM)

// pre-packed weights: [kk*32+co][40 halves] (32 ci + 8 pad)
__device__ __align__(16) __half w_packed[288 * 40];

__device__ __forceinline__ uint32_t smem_u32(const void* p) {
    uint32_t a;
    asm("{ .reg .u64 t; cvta.to.shared.u64 t, %1; cvt.u32.u64 %0, t; }"
        : "=r"(a) : "l"(p));
    return a;
}
__device__ __forceinline__ uint32_t h2u(__half2 h) {
    return *reinterpret_cast<uint32_t*>(&h);
}

#define STS128(addr, a, b, c, d) \
    asm volatile("st.shared.v4.b32 [%0], {%1,%2,%3,%4};" \
        :: "r"(addr), "r"(a), "r"(b), "r"(c), "r"(d) : "memory")

#define LDSM4(r, addr) \
    asm volatile("ldmatrix.sync.aligned.m8n8.x4.shared.b16 {%0,%1,%2,%3}, [%4];" \
        : "=r"((r)[0]), "=r"((r)[1]), "=r"((r)[2]), "=r"((r)[3]) : "r"(addr))

#define MMA_F16(c, a, b0, b1) \
    asm volatile("mma.sync.aligned.m16n8k16.row.col.f32.f16.f16.f32 " \
        "{%0,%1,%2,%3}, {%4,%5,%6,%7}, {%8,%9}, {%0,%1,%2,%3};" \
        : "+f"((c)[0]), "+f"((c)[1]), "+f"((c)[2]), "+f"((c)[3]) \
        : "r"((a)[0]), "r"((a)[1]), "r"((a)[2]), "r"((a)[3]), "r"(b0), "r"(b1))

#define CP_ASYNC16(smem, gmem) \
    asm volatile("cp.async.cg.shared.global [%0], [%1], 16;" \
        :: "r"(smem), "l"(gmem) : "memory")
#define CP_COMMIT()  asm volatile("cp.async.commit_group;" ::: "memory")
#define CP_WAIT0()   asm volatile("cp.async.wait_group 0;" ::: "memory")

// =====================================================================
// setup: w (OIHW fp32) -> w_packed [kk][co][ci] fp16
// =====================================================================
__global__ void pack_w_kernel(const float* __restrict__ w)
{
    int i = blockIdx.x * 256 + threadIdx.x;
    if (i < 288 * 32) {
        int row = i >> 5;                  // kk*32+co
        int ci  = i & 31;
        int kk  = row >> 5;
        int co  = row & 31;
        w_packed[row * 40 + ci] = __float2half_rn(w[(co * 32 + ci) * 9 + kk]);
    }
}

// =====================================================================
// main kernel helpers
// =====================================================================
// cp.async nrows raw fp32 input rows [base_row..) into the fp32 stage
__device__ __forceinline__ void issue_rows(const float* __restrict__ x,
                                           uint32_t sb, int nb, int x0,
                                           int base_row, int nrows, int t)
{
    const int nchunks = nrows * 32 * 17;      // 17 x 16B chunks per 68-px row
    #pragma unroll 1
    for (int chunk = t; chunk < nchunks; chunk += THREADS) {
        const int k   = chunk % 17;
        const int rem = chunk / 17;
        const int ci  = rem & 31;
        const int j   = rem >> 5;
        const int y_in = base_row + j;
        const int gx0  = x0 + k * 4;
        if (y_in < HIN && gx0 + 3 < WIN) {
            const float* g =
                x + ((size_t)(nb * CIN + ci) * HIN + y_in) * WIN + gx0;
            CP_ASYNC16(sb + F_OFF + (uint32_t)((j * 32 + ci) * FROW + k * 16), g);
        }
    }
}

// convert stage rows -> fp16 ring slots (slot = global_row % RSLOTS)
__device__ __forceinline__ void convert_rows(const char* smem, uint32_t sb,
                                             int base_row, int nrows, int t)
{
    const float* fs = reinterpret_cast<const float*>(smem + F_OFF);
    const int items = nrows * 4 * XPX;        // (j, octet, px)
    #pragma unroll 1
    for (int it = t; it < items; it += THREADS) {
        const int px  = it % XPX;
        const int rem = it / XPX;
        const int o   = rem & 3;
        const int j   = rem >> 2;
        const int slot = (base_row + j) % RSLOTS;
        const float* src = fs + (j * 32 + o * 8) * XPX + px;
        float v[8];
        #pragma unroll
        for (int q = 0; q < 8; ++q) v[q] = src[q * XPX];
        __half2 h0 = __floats2half2_rn(v[0], v[1]);
        __half2 h1 = __floats2half2_rn(v[2], v[3]);
        __half2 h2 = __floats2half2_rn(v[4], v[5]);
        __half2 h3 = __floats2half2_rn(v[6], v[7]);
        STS128(sb + (uint32_t)slot * XSLOT + (uint32_t)px * ROWB + (uint32_t)o * 16,
               h2u(h0), h2u(h1), h2u(h2), h2u(h3));
    }
}

// =====================================================================
// main kernel: fused-convert ring-buffered persistent fp16 implicit GEMM
// =====================================================================
__global__ __launch_bounds__(THREADS, 2)
void conv_mma_kernel(const float* __restrict__ x,
                     const float* __restrict__ bias,
                     float* __restrict__ out)
{
    extern __shared__ char smem[];
    const uint32_t sb = smem_u32(smem);
    const int t    = threadIdx.x;
    const int wid  = t >> 5;
    const int lane = t & 31;

    const int xt  = blockIdx.x;           // 0..7
    const int gy  = blockIdx.y;           // 0..15
    const int nb  = blockIdx.z;           // 0..15
    const int x0  = xt * TPX;
    const int yt0 = gy * NTILES;
    const int row0 = yt0 * TY;

    // ---- stage W once per CTA
    {
        const uint4* src = reinterpret_cast<const uint4*>(w_packed);
        #pragma unroll 1
        for (int i = t; i < W_BYTES / 16; i += THREADS) {
            uint4 v = src[i];
            STS128(sb + W_OFF + (uint32_t)i * 16, v.x, v.y, v.z, v.w);
        }
    }

    // ---- prologue: rows row0..row0+3, then row0+4..row0+5
    issue_rows(x, sb, nb, x0, row0, 4, t);
    CP_COMMIT(); CP_WAIT0(); __syncthreads();
    convert_rows(smem, sb, row0, 4, t);
    __syncthreads();
    issue_rows(x, sb, nb, x0, row0 + 4, 2, t);
    CP_COMMIT(); CP_WAIT0(); __syncthreads();
    convert_rows(smem, sb, row0 + 4, 2, t);
    __syncthreads();

    // lane constants
    const int a_row   = lane & 15;
    const int a_chunk = lane >> 4;
    const int b_n     = (lane & 7) | ((lane >> 4) << 3);
    const int b_chunk = (lane >> 3) & 1;
    const int g  = lane >> 2;
    const int tg = lane & 3;

    const int r   = wid >> 1;          // output row 0..3
    const int pxw = (wid & 1) * 32;    // px chunk base

    float bv[2][2];
    #pragma unroll
    for (int mt = 0; mt < 2; ++mt) {
        bv[mt][0] = __ldg(bias + mt * 16 + g);
        bv[mt][1] = __ldg(bias + mt * 16 + 8 + g);
    }

    #pragma unroll 1
    for (int i = 0; i < NTILES; ++i) {
        const int yin0 = (yt0 + i) * TY;

        // ---- prefetch the 4 rows tile i+1 needs beyond the overlap
        if (i + 1 < NTILES) {
            issue_rows(x, sb, nb, x0, yin0 + 6, 4, t);
            CP_COMMIT();
        }

        // ---- compute tile i (ring slots (yin0+r+ky) % RSLOTS)
        float c[2][4][4];
        #pragma unroll
        for (int mt = 0; mt < 2; ++mt)
            #pragma unroll
            for (int q = 0; q < 4; ++q) {
                c[mt][q][0] = bv[mt][0]; c[mt][q][1] = bv[mt][0];
                c[mt][q][2] = bv[mt][1]; c[mt][q][3] = bv[mt][1];
            }

        #pragma unroll
        for (int ky = 0; ky < 3; ++ky) {
            const int srow = yin0 + r + ky;
            const uint32_t Xs = sb + (uint32_t)(srow % RSLOTS) * XSLOT;
            #pragma unroll
            for (int kx = 0; kx < 3; ++kx) {
                const int kk = ky * 3 + kx;
                const uint32_t aBase =
                    sb + W_OFF + (uint32_t)(kk * 32 + a_row) * ROWB;
                #pragma unroll
                for (int kc = 0; kc < 2; ++kc) {
                    const uint32_t aOff = (uint32_t)(2 * kc + a_chunk) * 16;
                    const uint32_t bOff = (uint32_t)(2 * kc + b_chunk) * 16;

                    uint32_t a[2][4];
                    LDSM4(a[0], aBase + aOff);
                    LDSM4(a[1], aBase + 16 * ROWB + aOff);

                    uint32_t b[2][4];
                    #pragma unroll
                    for (int g2 = 0; g2 < 2; ++g2) {
                        const int prow = pxw + kx + g2 * 16 + b_n;
                        LDSM4(b[g2], Xs + (uint32_t)prow * ROWB + bOff);
                    }
                    #pragma unroll
                    for (int mt = 0; mt < 2; ++mt)
                        #pragma unroll
                        for (int q = 0; q < 4; ++q) {
                            const int g2 = q >> 1;
                            const int e  = (q & 1) * 2;
                            MMA_F16(c[mt][q], a[mt], b[g2][e], b[g2][e + 1]);
                        }
                }
            }
        }

        // ---- store
        const int oy = yin0 + r;
        if (oy < HOUT) {
            #pragma unroll
            for (int mt = 0; mt < 2; ++mt) {
                const size_t base0 =
                    ((size_t)(nb * COUT + mt * 16 + g) * HOUT + oy) * (size_t)WOUT;
                const size_t coStep = (size_t)8 * HOUT * WOUT;
                #pragma unroll
                for (int q = 0; q < 4; ++q) {
                    const int ox = x0 + pxw + q * 8 + 2 * tg;
                    if (ox < WOUT) {
                        float2 v0 = make_float2(c[mt][q][0], c[mt][q][1]);
                        float2 v1 = make_float2(c[mt][q][2], c[mt][q][3]);
                        *reinterpret_cast<float2*>(out + base0 + ox)          = v0;
                        *reinterpret_cast<float2*>(out + base0 + coStep + ox) = v1;
                    }
                }
            }
        }

        // ---- drain prefetch, convert into ring, flip
        if (i + 1 < NTILES) {
            CP_WAIT0();
            __syncthreads();
            convert_rows(smem, sb, yin0 + 6, 4, t);
        }
        __syncthreads();
    }
}

extern "C" void kernel_launch(void* const* d_in, const int* in_sizes, int n_in,
                              void* d_out, int out_size)
{
    const float* x    = (const float*)d_in[0];
    const float* w    = (const float*)d_in[1];
    const float* bias = (const float*)d_in[2];
    float*       out  = (float*)d_out;

    pack_w_kernel<<<36, 256>>>(w);

    cudaFuncSetAttribute(conv_mma_kernel,
                         cudaFuncAttributeMaxDynamicSharedMemorySize, SMEM_TOTAL);

    dim3 grid(8, 16, NB);               // 8 x-tiles, 16 y-walks, 16 batches
    conv_mma_kernel<<<grid, THREADS, SMEM_TOTAL>>>(x, bias, out);
}